// round 1
// baseline (speedup 1.0000x reference)
#include <cuda_runtime.h>
#include <cstdint>

#define Bq 2
#define Tq 1024
#define Eq 1024
#define Hq 16
#define Dq 64
#define Lq 6
#define FFq 4096
#define Vq 32000

// ---------------- scratch (device globals; no runtime allocation) ----------
__device__ float g_x [Bq*Tq*Eq];
__device__ float g_h [Bq*Tq*Eq];
__device__ float g_q [Bq*Tq*Eq];
__device__ float g_k [Bq*Tq*Eq];
__device__ float g_v [Bq*Tq*Eq];
__device__ float g_o [Bq*Tq*Eq];
__device__ float g_ff[Bq*Tq*FFq];
__device__ float g_att[(size_t)Bq*Hq*Tq*Tq];

// ---------------- block reductions (256 threads) ----------------------------
__device__ __forceinline__ float block_reduce_sum(float v) {
    __shared__ float sh[8];
    #pragma unroll
    for (int o = 16; o > 0; o >>= 1) v += __shfl_xor_sync(0xffffffffu, v, o);
    int lane = threadIdx.x & 31, w = threadIdx.x >> 5;
    if (lane == 0) sh[w] = v;
    __syncthreads();
    float r = (lane < 8) ? sh[lane] : 0.f;
    #pragma unroll
    for (int o = 4; o > 0; o >>= 1) r += __shfl_xor_sync(0xffffffffu, r, o);
    r = __shfl_sync(0xffffffffu, r, 0);
    __syncthreads();
    return r;
}

__device__ __forceinline__ float block_reduce_max(float v) {
    __shared__ float sh[8];
    #pragma unroll
    for (int o = 16; o > 0; o >>= 1) v = fmaxf(v, __shfl_xor_sync(0xffffffffu, v, o));
    int lane = threadIdx.x & 31, w = threadIdx.x >> 5;
    if (lane == 0) sh[w] = v;
    __syncthreads();
    float r = (lane < 8) ? sh[lane] : -1e30f;
    #pragma unroll
    for (int o = 4; o > 0; o >>= 1) r = fmaxf(r, __shfl_xor_sync(0xffffffffu, r, o));
    r = __shfl_sync(0xffffffffu, r, 0);
    __syncthreads();
    return r;
}

// ---------------- embedding --------------------------------------------------
__global__ __launch_bounds__(256) void embed_kernel(
    const int* __restrict__ idx, const float* __restrict__ tok_w,
    const float* __restrict__ pos, float* __restrict__ x)
{
    int i = blockIdx.x * 256 + threadIdx.x;          // over B*T*E/4 float4s
    const int E4 = Eq / 4;
    int e4 = i % E4;
    int bt = i / E4;
    int t  = bt % Tq;
    int tok = idx[bt];
    float4 tw = ((const float4*)tok_w)[(int64_t)tok * E4 + e4];
    float4 pe = ((const float4*)pos)[(int64_t)t * E4 + e4];
    ((float4*)x)[i] = make_float4(tw.x + pe.x, tw.y + pe.y, tw.z + pe.z, tw.w + pe.w);
}

// ---------------- layernorm (one block per row of E=1024) -------------------
__global__ __launch_bounds__(256) void ln_kernel(
    const float* __restrict__ x, float* __restrict__ y,
    const float* __restrict__ s, const float* __restrict__ b)
{
    int row = blockIdx.x;
    int tid = threadIdx.x;
    const float4* xr = (const float4*)(x + (int64_t)row * Eq);
    float4 v = xr[tid];
    float tot = block_reduce_sum(v.x + v.y + v.z + v.w);
    float mean = tot * (1.f / Eq);
    float dx = v.x - mean, dy = v.y - mean, dz = v.z - mean, dw = v.w - mean;
    float tot2 = block_reduce_sum(dx*dx + dy*dy + dz*dz + dw*dw);
    float inv = rsqrtf(tot2 * (1.f / Eq) + 1e-5f);
    float4 sv = ((const float4*)s)[tid];
    float4 bv = ((const float4*)b)[tid];
    float4 o;
    o.x = dx * inv * sv.x + bv.x;
    o.y = dy * inv * sv.y + bv.y;
    o.z = dz * inv * sv.z + bv.z;
    o.w = dw * inv * sv.w + bv.w;
    ((float4*)(y + (int64_t)row * Eq))[tid] = o;
}

// ---------------- causal softmax (one block per attention row) --------------
__global__ __launch_bounds__(256) void softmax_causal(float* __restrict__ att)
{
    int r = blockIdx.x;              // 0 .. B*H*T-1
    int t = r % Tq;
    float* row = att + (int64_t)r * Tq;
    int tid = threadIdx.x;
    int c0 = tid * 4;
    float4 v = ((const float4*)row)[tid];
    float vals[4] = {v.x, v.y, v.z, v.w};
    float m = -1e30f;
    #pragma unroll
    for (int i = 0; i < 4; i++) if (c0 + i <= t) m = fmaxf(m, vals[i]);
    float mx = block_reduce_max(m);
    float e[4]; float s = 0.f;
    #pragma unroll
    for (int i = 0; i < 4; i++) {
        e[i] = (c0 + i <= t) ? __expf(vals[i] - mx) : 0.f;
        s += e[i];
    }
    float tot = block_reduce_sum(s);
    float inv = 1.f / tot;
    ((float4*)row)[tid] = make_float4(e[0]*inv, e[1]*inv, e[2]*inv, e[3]*inv);
}

// ---------------- generic tiled GEMM -----------------------------------------
// C = alpha * A @ B (+bias[n]) (+resid) (ReLU optional)
// A: M x K, row-major, lda
// B: if !TB, K x N row-major (off = k*ldb + n); if TB, element (k,n) at n*ldb + k
// Two-level batching via blockIdx.z: zi = z % batch_inner, zo = z / batch_inner
template<bool TB>
__global__ __launch_bounds__(256, 2) void gemm_k(
    const float* __restrict__ A, const float* __restrict__ Bm, float* __restrict__ C,
    int M, int N, int K, int lda, int ldb, int ldc,
    int batch_inner,
    long long sAi, long long sAo, long long sBi, long long sBo,
    long long sCi, long long sCo,
    const float* __restrict__ bias, const float* __restrict__ resid,
    int relu, float alpha)
{
    constexpr int BM = 128, BN = 128, BK = 16;
    __shared__ float As[BK][BM + 4];
    __shared__ float Bs[BK][BN + 4];

    int zi = blockIdx.z % batch_inner;
    int zo = blockIdx.z / batch_inner;
    A  += (int64_t)zi * sAi + (int64_t)zo * sAo;
    Bm += (int64_t)zi * sBi + (int64_t)zo * sBo;
    int64_t cbase = (int64_t)zi * sCi + (int64_t)zo * sCo;

    int row0 = blockIdx.y * BM;
    int col0 = blockIdx.x * BN;
    int tid = threadIdx.x;
    int tx = tid & 15, ty = tid >> 4;

    float acc[8][8];
    #pragma unroll
    for (int i = 0; i < 8; i++)
        #pragma unroll
        for (int j = 0; j < 8; j++) acc[i][j] = 0.f;

    for (int k0 = 0; k0 < K; k0 += BK) {
        // ---- load A tile (BM x BK) : 512 float4, 2 per thread ----
        #pragma unroll
        for (int it = 0; it < 2; it++) {
            int idx = tid + it * 256;
            int m  = idx >> 2;
            int kq = idx & 3;
            float4 av = make_float4(0.f, 0.f, 0.f, 0.f);
            if (row0 + m < M)
                av = *(const float4*)(A + (int64_t)(row0 + m) * lda + k0 + kq * 4);
            As[kq*4 + 0][m] = av.x;
            As[kq*4 + 1][m] = av.y;
            As[kq*4 + 2][m] = av.z;
            As[kq*4 + 3][m] = av.w;
        }
        // ---- load B tile (BK x BN) ----
        #pragma unroll
        for (int it = 0; it < 2; it++) {
            int idx = tid + it * 256;
            if (!TB) {
                int n4 = idx & 31;        // BN/4
                int kk = idx >> 5;        // 0..15
                int n = col0 + n4 * 4;
                float4 bv = make_float4(0.f, 0.f, 0.f, 0.f);
                if (n + 3 < N)
                    bv = *(const float4*)(Bm + (int64_t)(k0 + kk) * ldb + n);
                *(float4*)&Bs[kk][n4 * 4] = bv;
            } else {
                int kq = idx & 3;
                int n  = idx >> 2;        // 0..127
                float4 bv = make_float4(0.f, 0.f, 0.f, 0.f);
                if (col0 + n < N)
                    bv = *(const float4*)(Bm + (int64_t)(col0 + n) * ldb + k0 + kq * 4);
                Bs[kq*4 + 0][n] = bv.x;
                Bs[kq*4 + 1][n] = bv.y;
                Bs[kq*4 + 2][n] = bv.z;
                Bs[kq*4 + 3][n] = bv.w;
            }
        }
        __syncthreads();

        #pragma unroll
        for (int kk = 0; kk < BK; kk++) {
            float4 a0 = *(const float4*)&As[kk][ty * 4];
            float4 a1 = *(const float4*)&As[kk][64 + ty * 4];
            float4 b0 = *(const float4*)&Bs[kk][tx * 4];
            float4 b1 = *(const float4*)&Bs[kk][64 + tx * 4];
            float ar[8] = {a0.x, a0.y, a0.z, a0.w, a1.x, a1.y, a1.z, a1.w};
            float br[8] = {b0.x, b0.y, b0.z, b0.w, b1.x, b1.y, b1.z, b1.w};
            #pragma unroll
            for (int i = 0; i < 8; i++)
                #pragma unroll
                for (int j = 0; j < 8; j++)
                    acc[i][j] = fmaf(ar[i], br[j], acc[i][j]);
        }
        __syncthreads();
    }

    // ---- epilogue ----
    float* Cp = C + cbase;
    const float* Rp = resid ? (resid + cbase) : nullptr;
    #pragma unroll
    for (int i = 0; i < 8; i++) {
        int r = row0 + ((i < 4) ? (ty * 4 + i) : (64 + ty * 4 + (i - 4)));
        if (r >= M) continue;
        #pragma unroll
        for (int j = 0; j < 8; j++) {
            int c = col0 + ((j < 4) ? (tx * 4 + j) : (64 + tx * 4 + (j - 4)));
            if (c >= N) continue;
            float val = alpha * acc[i][j];
            if (bias) val += bias[c];
            if (Rp)   val += Rp[(int64_t)r * ldc + c];
            if (relu) val = fmaxf(val, 0.f);
            Cp[(int64_t)r * ldc + c] = val;
        }
    }
}

// ---------------- host orchestration ----------------------------------------
static inline dim3 ggrid(int M, int N, int batch) {
    return dim3((unsigned)((N + 127) / 128), (unsigned)((M + 127) / 128), (unsigned)batch);
}

extern "C" void kernel_launch(void* const* d_in, const int* in_sizes, int n_in,
                              void* d_out, int out_size)
{
    const int*   idx    = (const int*)  d_in[0];
    const float* tok_w  = (const float*)d_in[1];
    const float* pos    = (const float*)d_in[2];
    const float* ln1_s  = (const float*)d_in[3];
    const float* ln1_b  = (const float*)d_in[4];
    const float* wq     = (const float*)d_in[5];
    const float* wk     = (const float*)d_in[6];
    const float* wv     = (const float*)d_in[7];
    const float* wo     = (const float*)d_in[8];
    const float* bo     = (const float*)d_in[9];
    const float* ln2_s  = (const float*)d_in[10];
    const float* ln2_b  = (const float*)d_in[11];
    const float* w1     = (const float*)d_in[12];
    const float* b1     = (const float*)d_in[13];
    const float* w2     = (const float*)d_in[14];
    const float* b2     = (const float*)d_in[15];
    const float* lnf_s  = (const float*)d_in[16];
    const float* lnf_b  = (const float*)d_in[17];
    const float* head_w = (const float*)d_in[18];
    const float* head_b = (const float*)d_in[19];
    float* out = (float*)d_out;

    float *x, *h, *q, *k, *v, *o, *ff, *att;
    cudaGetSymbolAddress((void**)&x,   g_x);
    cudaGetSymbolAddress((void**)&h,   g_h);
    cudaGetSymbolAddress((void**)&q,   g_q);
    cudaGetSymbolAddress((void**)&k,   g_k);
    cudaGetSymbolAddress((void**)&v,   g_v);
    cudaGetSymbolAddress((void**)&o,   g_o);
    cudaGetSymbolAddress((void**)&ff,  g_ff);
    cudaGetSymbolAddress((void**)&att, g_att);

    const int M = Bq * Tq;                  // 2048
    const float scale = 0.125f;             // 1/sqrt(64)

    // embedding
    embed_kernel<<<(M * Eq / 4 + 255) / 256, 256>>>(idx, tok_w, pos, x);

    for (int l = 0; l < Lq; l++) {
        const float* Wq = wq + (int64_t)l * Eq * Eq;
        const float* Wk = wk + (int64_t)l * Eq * Eq;
        const float* Wv = wv + (int64_t)l * Eq * Eq;
        const float* Wo = wo + (int64_t)l * Eq * Eq;
        const float* W1 = w1 + (int64_t)l * Eq * FFq;
        const float* W2 = w2 + (int64_t)l * FFq * Eq;

        // ln1
        ln_kernel<<<M, 256>>>(x, h, ln1_s + l * Eq, ln1_b + l * Eq);

        // q, k, v projections
        gemm_k<false><<<ggrid(M, Eq, 1), 256>>>(h, Wq, q, M, Eq, Eq, Eq, Eq, Eq,
            1, 0,0,0,0,0,0, nullptr, nullptr, 0, 1.0f);
        gemm_k<false><<<ggrid(M, Eq, 1), 256>>>(h, Wk, k, M, Eq, Eq, Eq, Eq, Eq,
            1, 0,0,0,0,0,0, nullptr, nullptr, 0, 1.0f);
        gemm_k<false><<<ggrid(M, Eq, 1), 256>>>(h, Wv, v, M, Eq, Eq, Eq, Eq, Eq,
            1, 0,0,0,0,0,0, nullptr, nullptr, 0, 1.0f);

        // scores: att[b,h,t,s] = scale * q . k   (batched over B*H, B^T form)
        gemm_k<true><<<ggrid(Tq, Tq, Bq * Hq), 256>>>(q, k, att,
            Tq, Tq, Dq, Eq, Eq, Tq,
            Hq,
            /*sAi*/ Dq, /*sAo*/ (long long)Tq * Eq,
            /*sBi*/ Dq, /*sBo*/ (long long)Tq * Eq,
            /*sCi*/ (long long)Tq * Tq, /*sCo*/ (long long)Hq * Tq * Tq,
            nullptr, nullptr, 0, scale);

        // causal softmax
        softmax_causal<<<Bq * Hq * Tq, 256>>>(att);

        // o = att @ v  (batched over B*H)
        gemm_k<false><<<ggrid(Tq, Dq, Bq * Hq), 256>>>(att, v, o,
            Tq, Dq, Tq, Tq, Eq, Eq,
            Hq,
            /*sAi*/ (long long)Tq * Tq, /*sAo*/ (long long)Hq * Tq * Tq,
            /*sBi*/ Dq, /*sBo*/ (long long)Tq * Eq,
            /*sCi*/ Dq, /*sCo*/ (long long)Tq * Eq,
            nullptr, nullptr, 0, 1.0f);

        // x = x + o @ Wo + bo
        gemm_k<false><<<ggrid(M, Eq, 1), 256>>>(o, Wo, x, M, Eq, Eq, Eq, Eq, Eq,
            1, 0,0,0,0,0,0, bo + l * Eq, x, 0, 1.0f);

        // ln2
        ln_kernel<<<M, 256>>>(x, h, ln2_s + l * Eq, ln2_b + l * Eq);

        // ff = relu(h @ W1 + b1)
        gemm_k<false><<<ggrid(M, FFq, 1), 256>>>(h, W1, ff, M, FFq, Eq, Eq, FFq, FFq,
            1, 0,0,0,0,0,0, b1 + l * FFq, nullptr, 1, 1.0f);

        // x = x + ff @ W2 + b2
        gemm_k<false><<<ggrid(M, Eq, 1), 256>>>(ff, W2, x, M, Eq, FFq, FFq, Eq, Eq,
            1, 0,0,0,0,0,0, b2 + l * Eq, x, 0, 1.0f);
    }

    // final layernorm
    ln_kernel<<<M, 256>>>(x, h, lnf_s, lnf_b);

    // logits = h @ head_w + head_b
    gemm_k<false><<<ggrid(M, Vq, 1), 256>>>(h, head_w, out, M, Vq, Eq, Eq, Vq, Vq,
        1, 0,0,0,0,0,0, head_b, nullptr, 0, 1.0f);
}

// round 2
// speedup vs baseline: 2.2421x; 2.2421x over previous
#include <cuda_runtime.h>
#include <cstdint>

#define Bq 2
#define Tq 1024
#define Eq 1024
#define Hq 16
#define Dq 64
#define Lq 6
#define FFq 4096
#define Vq 32000

// ---------------- scratch (device globals; no runtime allocation) ----------
__device__ float g_x [Bq*Tq*Eq];
__device__ float g_h [Bq*Tq*Eq];
__device__ float g_q [Bq*Tq*Eq];
__device__ float g_k [Bq*Tq*Eq];
__device__ float g_v [Bq*Tq*Eq];
__device__ float g_o [Bq*Tq*Eq];
__device__ float g_ff[Bq*Tq*FFq];
__device__ float g_att[(size_t)Bq*Hq*Tq*Tq];

// ---------------- block reductions (256 threads) ----------------------------
__device__ __forceinline__ float block_reduce_sum(float v) {
    __shared__ float sh[8];
    #pragma unroll
    for (int o = 16; o > 0; o >>= 1) v += __shfl_xor_sync(0xffffffffu, v, o);
    int lane = threadIdx.x & 31, w = threadIdx.x >> 5;
    if (lane == 0) sh[w] = v;
    __syncthreads();
    float r = (lane < 8) ? sh[lane] : 0.f;
    #pragma unroll
    for (int o = 4; o > 0; o >>= 1) r += __shfl_xor_sync(0xffffffffu, r, o);
    r = __shfl_sync(0xffffffffu, r, 0);
    __syncthreads();
    return r;
}

__device__ __forceinline__ float block_reduce_max(float v) {
    __shared__ float sh[8];
    #pragma unroll
    for (int o = 16; o > 0; o >>= 1) v = fmaxf(v, __shfl_xor_sync(0xffffffffu, v, o));
    int lane = threadIdx.x & 31, w = threadIdx.x >> 5;
    if (lane == 0) sh[w] = v;
    __syncthreads();
    float r = (lane < 8) ? sh[lane] : -1e30f;
    #pragma unroll
    for (int o = 4; o > 0; o >>= 1) r = fmaxf(r, __shfl_xor_sync(0xffffffffu, r, o));
    r = __shfl_sync(0xffffffffu, r, 0);
    __syncthreads();
    return r;
}

// ---------------- embedding --------------------------------------------------
__global__ __launch_bounds__(256) void embed_kernel(
    const int* __restrict__ idx, const float* __restrict__ tok_w,
    const float* __restrict__ pos, float* __restrict__ x)
{
    int i = blockIdx.x * 256 + threadIdx.x;          // over B*T*E/4 float4s
    const int E4 = Eq / 4;
    int e4 = i % E4;
    int bt = i / E4;
    int t  = bt % Tq;
    int tok = idx[bt];
    float4 tw = ((const float4*)tok_w)[(int64_t)tok * E4 + e4];
    float4 pe = ((const float4*)pos)[(int64_t)t * E4 + e4];
    ((float4*)x)[i] = make_float4(tw.x + pe.x, tw.y + pe.y, tw.z + pe.z, tw.w + pe.w);
}

// ---------------- layernorm (one block per row of E=1024) -------------------
__global__ __launch_bounds__(256) void ln_kernel(
    const float* __restrict__ x, float* __restrict__ y,
    const float* __restrict__ s, const float* __restrict__ b)
{
    int row = blockIdx.x;
    int tid = threadIdx.x;
    const float4* xr = (const float4*)(x + (int64_t)row * Eq);
    float4 v = xr[tid];
    float tot = block_reduce_sum(v.x + v.y + v.z + v.w);
    float mean = tot * (1.f / Eq);
    float dx = v.x - mean, dy = v.y - mean, dz = v.z - mean, dw = v.w - mean;
    float tot2 = block_reduce_sum(dx*dx + dy*dy + dz*dz + dw*dw);
    float inv = rsqrtf(tot2 * (1.f / Eq) + 1e-5f);
    float4 sv = ((const float4*)s)[tid];
    float4 bv = ((const float4*)b)[tid];
    float4 o;
    o.x = dx * inv * sv.x + bv.x;
    o.y = dy * inv * sv.y + bv.y;
    o.z = dz * inv * sv.z + bv.z;
    o.w = dw * inv * sv.w + bv.w;
    ((float4*)(y + (int64_t)row * Eq))[tid] = o;
}

// ---------------- causal softmax (one block per attention row) --------------
__global__ __launch_bounds__(256) void softmax_causal(float* __restrict__ att)
{
    int r = blockIdx.x;              // 0 .. B*H*T-1
    int t = r % Tq;
    float* row = att + (int64_t)r * Tq;
    int tid = threadIdx.x;
    int c0 = tid * 4;
    float4 v = ((const float4*)row)[tid];
    float vals[4] = {v.x, v.y, v.z, v.w};
    float m = -1e30f;
    #pragma unroll
    for (int i = 0; i < 4; i++) if (c0 + i <= t) m = fmaxf(m, vals[i]);
    float mx = block_reduce_max(m);
    float e[4]; float s = 0.f;
    #pragma unroll
    for (int i = 0; i < 4; i++) {
        e[i] = (c0 + i <= t) ? __expf(vals[i] - mx) : 0.f;
        s += e[i];
    }
    float tot = block_reduce_sum(s);
    float inv = 1.f / tot;
    ((float4*)row)[tid] = make_float4(e[0]*inv, e[1]*inv, e[2]*inv, e[3]*inv);
}

// ---------------- tf32 helpers -----------------------------------------------
__device__ __forceinline__ uint32_t f2tf(float f) {
    uint32_t u;
    asm("cvt.rna.tf32.f32 %0, %1;" : "=r"(u) : "f"(f));
    return u;
}

#define MMA_TF32(c, a, b)                                                     \
    asm volatile(                                                             \
        "mma.sync.aligned.m16n8k8.row.col.f32.tf32.tf32.f32 "                 \
        "{%0,%1,%2,%3}, {%4,%5,%6,%7}, {%8,%9}, {%0,%1,%2,%3};"               \
        : "+f"(c[0]), "+f"(c[1]), "+f"(c[2]), "+f"(c[3])                      \
        : "r"(a[0]), "r"(a[1]), "r"(a[2]), "r"(a[3]), "r"(b[0]), "r"(b[1]))

// ---------------- TF32 tensor-core GEMM --------------------------------------
// C = alpha * A @ B (+bias[n]) (+resid) (ReLU optional)
// A: M x K row-major (lda). B: !TB -> K x N row-major (ldb); TB -> (k,n) at n*ldb+k.
// Block tile 128x128x16, 8 warps of 64x32, double-buffered smem, reg-staged prefetch.
template<bool TB>
__global__ __launch_bounds__(256, 2) void gemm_tc(
    const float* __restrict__ A, const float* __restrict__ Bm, float* __restrict__ C,
    int M, int N, int K, int lda, int ldb, int ldc,
    int batch_inner,
    long long sAi, long long sAo, long long sBi, long long sBo,
    long long sCi, long long sCo,
    const float* __restrict__ bias, const float* __restrict__ resid,
    int relu, float alpha)
{
    __shared__ uint32_t As[2][16][132];
    __shared__ uint32_t Bs[2][16][132];

    int zi = blockIdx.z % batch_inner;
    int zo = blockIdx.z / batch_inner;
    A  += (int64_t)zi * sAi + (int64_t)zo * sAo;
    Bm += (int64_t)zi * sBi + (int64_t)zo * sBo;
    int64_t cbase = (int64_t)zi * sCi + (int64_t)zo * sCo;

    int row0 = blockIdx.y * 128;
    int col0 = blockIdx.x * 128;
    int tid  = threadIdx.x;
    int warp = tid >> 5, lane = tid & 31;
    int g = lane >> 2, t = lane & 3;
    int wM = (warp & 1) * 64;    // warp row offset within block tile
    int wN = (warp >> 1) * 32;   // warp col offset within block tile

    float acc[4][4][4];
    #pragma unroll
    for (int i = 0; i < 4; i++)
        #pragma unroll
        for (int j = 0; j < 4; j++)
            #pragma unroll
            for (int e = 0; e < 4; e++) acc[i][j][e] = 0.f;

    const int aM  = tid >> 2;    // 0..63
    const int akq = tid & 3;     // 0..3

    float4 stA[2], stB[2];

    auto loadg = [&](int k0) {
        #pragma unroll
        for (int it = 0; it < 2; it++) {
            int m = aM + it * 64;
            float4 v = make_float4(0.f, 0.f, 0.f, 0.f);
            if (row0 + m < M)
                v = *(const float4*)(A + (int64_t)(row0 + m) * lda + k0 + akq * 4);
            stA[it] = v;
        }
        #pragma unroll
        for (int it = 0; it < 2; it++) {
            float4 v = make_float4(0.f, 0.f, 0.f, 0.f);
            if (!TB) {
                int n4 = tid & 31;
                int kk = (tid >> 5) + it * 8;
                int n  = col0 + n4 * 4;
                if (n + 3 < N)
                    v = *(const float4*)(Bm + (int64_t)(k0 + kk) * ldb + n);
            } else {
                int n = (tid >> 2) + it * 64;
                if (col0 + n < N)
                    v = *(const float4*)(Bm + (int64_t)(col0 + n) * ldb + k0 + akq * 4);
            }
            stB[it] = v;
        }
    };

    auto stores = [&](int buf) {
        #pragma unroll
        for (int it = 0; it < 2; it++) {
            int m = aM + it * 64;
            As[buf][akq * 4 + 0][m] = f2tf(stA[it].x);
            As[buf][akq * 4 + 1][m] = f2tf(stA[it].y);
            As[buf][akq * 4 + 2][m] = f2tf(stA[it].z);
            As[buf][akq * 4 + 3][m] = f2tf(stA[it].w);
        }
        #pragma unroll
        for (int it = 0; it < 2; it++) {
            if (!TB) {
                int n4 = tid & 31;
                int kk = (tid >> 5) + it * 8;
                Bs[buf][kk][n4 * 4 + 0] = f2tf(stB[it].x);
                Bs[buf][kk][n4 * 4 + 1] = f2tf(stB[it].y);
                Bs[buf][kk][n4 * 4 + 2] = f2tf(stB[it].z);
                Bs[buf][kk][n4 * 4 + 3] = f2tf(stB[it].w);
            } else {
                int n = (tid >> 2) + it * 64;
                Bs[buf][akq * 4 + 0][n] = f2tf(stB[it].x);
                Bs[buf][akq * 4 + 1][n] = f2tf(stB[it].y);
                Bs[buf][akq * 4 + 2][n] = f2tf(stB[it].z);
                Bs[buf][akq * 4 + 3][n] = f2tf(stB[it].w);
            }
        }
    };

    auto compute = [&](int buf) {
        #pragma unroll
        for (int ks = 0; ks < 2; ks++) {
            int kb = ks * 8;
            uint32_t af[4][4], bf[4][2];
            #pragma unroll
            for (int i = 0; i < 4; i++) {
                int m = wM + i * 16 + g;
                af[i][0] = As[buf][kb + t][m];
                af[i][1] = As[buf][kb + t][m + 8];
                af[i][2] = As[buf][kb + t + 4][m];
                af[i][3] = As[buf][kb + t + 4][m + 8];
            }
            #pragma unroll
            for (int j = 0; j < 4; j++) {
                int n = wN + j * 8 + g;
                bf[j][0] = Bs[buf][kb + t][n];
                bf[j][1] = Bs[buf][kb + t + 4][n];
            }
            #pragma unroll
            for (int i = 0; i < 4; i++)
                #pragma unroll
                for (int j = 0; j < 4; j++)
                    MMA_TF32(acc[i][j], af[i], bf[j]);
        }
    };

    // pipeline: prologue
    loadg(0);
    stores(0);
    __syncthreads();

    int nit = K >> 4;
    int buf = 0;
    for (int itk = 1; itk < nit; itk++) {
        loadg(itk << 4);
        compute(buf);
        stores(buf ^ 1);
        __syncthreads();
        buf ^= 1;
    }
    compute(buf);

    // ---- epilogue ----
    float* Cp = C + cbase;
    const float* Rp = resid ? (resid + cbase) : nullptr;
    #pragma unroll
    for (int i = 0; i < 4; i++) {
        int r0 = row0 + wM + i * 16 + g;
        #pragma unroll
        for (int j = 0; j < 4; j++) {
            int c = col0 + wN + j * 8 + t * 2;
            if (c >= N) continue;
            #pragma unroll
            for (int half = 0; half < 2; half++) {
                int r = r0 + half * 8;
                if (r >= M) continue;
                float v0 = alpha * acc[i][j][half * 2 + 0];
                float v1 = alpha * acc[i][j][half * 2 + 1];
                if (bias) { v0 += bias[c]; v1 += bias[c + 1]; }
                if (Rp) {
                    float2 rv = *(const float2*)(Rp + (int64_t)r * ldc + c);
                    v0 += rv.x; v1 += rv.y;
                }
                if (relu) { v0 = fmaxf(v0, 0.f); v1 = fmaxf(v1, 0.f); }
                *(float2*)(Cp + (int64_t)r * ldc + c) = make_float2(v0, v1);
            }
        }
    }
}

// ---------------- host orchestration ----------------------------------------
static inline dim3 ggrid(int M, int N, int batch) {
    return dim3((unsigned)((N + 127) / 128), (unsigned)((M + 127) / 128), (unsigned)batch);
}

extern "C" void kernel_launch(void* const* d_in, const int* in_sizes, int n_in,
                              void* d_out, int out_size)
{
    const int*   idx    = (const int*)  d_in[0];
    const float* tok_w  = (const float*)d_in[1];
    const float* pos    = (const float*)d_in[2];
    const float* ln1_s  = (const float*)d_in[3];
    const float* ln1_b  = (const float*)d_in[4];
    const float* wq     = (const float*)d_in[5];
    const float* wk     = (const float*)d_in[6];
    const float* wv     = (const float*)d_in[7];
    const float* wo     = (const float*)d_in[8];
    const float* bo     = (const float*)d_in[9];
    const float* ln2_s  = (const float*)d_in[10];
    const float* ln2_b  = (const float*)d_in[11];
    const float* w1     = (const float*)d_in[12];
    const float* b1     = (const float*)d_in[13];
    const float* w2     = (const float*)d_in[14];
    const float* b2     = (const float*)d_in[15];
    const float* lnf_s  = (const float*)d_in[16];
    const float* lnf_b  = (const float*)d_in[17];
    const float* head_w = (const float*)d_in[18];
    const float* head_b = (const float*)d_in[19];
    float* out = (float*)d_out;

    float *x, *h, *q, *k, *v, *o, *ff, *att;
    cudaGetSymbolAddress((void**)&x,   g_x);
    cudaGetSymbolAddress((void**)&h,   g_h);
    cudaGetSymbolAddress((void**)&q,   g_q);
    cudaGetSymbolAddress((void**)&k,   g_k);
    cudaGetSymbolAddress((void**)&v,   g_v);
    cudaGetSymbolAddress((void**)&o,   g_o);
    cudaGetSymbolAddress((void**)&ff,  g_ff);
    cudaGetSymbolAddress((void**)&att, g_att);

    const int M = Bq * Tq;                  // 2048
    const float scale = 0.125f;             // 1/sqrt(64)

    // embedding
    embed_kernel<<<(M * Eq / 4 + 255) / 256, 256>>>(idx, tok_w, pos, x);

    for (int l = 0; l < Lq; l++) {
        const float* Wq = wq + (int64_t)l * Eq * Eq;
        const float* Wk = wk + (int64_t)l * Eq * Eq;
        const float* Wv = wv + (int64_t)l * Eq * Eq;
        const float* Wo = wo + (int64_t)l * Eq * Eq;
        const float* W1 = w1 + (int64_t)l * Eq * FFq;
        const float* W2 = w2 + (int64_t)l * FFq * Eq;

        // ln1
        ln_kernel<<<M, 256>>>(x, h, ln1_s + l * Eq, ln1_b + l * Eq);

        // q, k, v projections
        gemm_tc<false><<<ggrid(M, Eq, 1), 256>>>(h, Wq, q, M, Eq, Eq, Eq, Eq, Eq,
            1, 0,0,0,0,0,0, nullptr, nullptr, 0, 1.0f);
        gemm_tc<false><<<ggrid(M, Eq, 1), 256>>>(h, Wk, k, M, Eq, Eq, Eq, Eq, Eq,
            1, 0,0,0,0,0,0, nullptr, nullptr, 0, 1.0f);
        gemm_tc<false><<<ggrid(M, Eq, 1), 256>>>(h, Wv, v, M, Eq, Eq, Eq, Eq, Eq,
            1, 0,0,0,0,0,0, nullptr, nullptr, 0, 1.0f);

        // scores: att[b,h,t,s] = scale * q . k   (batched over B*H, B^T form)
        gemm_tc<true><<<ggrid(Tq, Tq, Bq * Hq), 256>>>(q, k, att,
            Tq, Tq, Dq, Eq, Eq, Tq,
            Hq,
            /*sAi*/ Dq, /*sAo*/ (long long)Tq * Eq,
            /*sBi*/ Dq, /*sBo*/ (long long)Tq * Eq,
            /*sCi*/ (long long)Tq * Tq, /*sCo*/ (long long)Hq * Tq * Tq,
            nullptr, nullptr, 0, scale);

        // causal softmax
        softmax_causal<<<Bq * Hq * Tq, 256>>>(att);

        // o = att @ v  (batched over B*H)
        gemm_tc<false><<<ggrid(Tq, Dq, Bq * Hq), 256>>>(att, v, o,
            Tq, Dq, Tq, Tq, Eq, Eq,
            Hq,
            /*sAi*/ (long long)Tq * Tq, /*sAo*/ (long long)Hq * Tq * Tq,
            /*sBi*/ Dq, /*sBo*/ (long long)Tq * Eq,
            /*sCi*/ Dq, /*sCo*/ (long long)Tq * Eq,
            nullptr, nullptr, 0, 1.0f);

        // x = x + o @ Wo + bo
        gemm_tc<false><<<ggrid(M, Eq, 1), 256>>>(o, Wo, x, M, Eq, Eq, Eq, Eq, Eq,
            1, 0,0,0,0,0,0, bo + l * Eq, x, 0, 1.0f);

        // ln2
        ln_kernel<<<M, 256>>>(x, h, ln2_s + l * Eq, ln2_b + l * Eq);

        // ff = relu(h @ W1 + b1)
        gemm_tc<false><<<ggrid(M, FFq, 1), 256>>>(h, W1, ff, M, FFq, Eq, Eq, FFq, FFq,
            1, 0,0,0,0,0,0, b1 + l * FFq, nullptr, 1, 1.0f);

        // x = x + ff @ W2 + b2
        gemm_tc<false><<<ggrid(M, Eq, 1), 256>>>(ff, W2, x, M, Eq, FFq, FFq, Eq, Eq,
            1, 0,0,0,0,0,0, b2 + l * Eq, x, 0, 1.0f);
    }

    // final layernorm
    ln_kernel<<<M, 256>>>(x, h, lnf_s, lnf_b);

    // logits = h @ head_w + head_b
    gemm_tc<false><<<ggrid(M, Vq, 1), 256>>>(h, head_w, out, M, Vq, Eq, Eq, Vq, Vq,
        1, 0,0,0,0,0,0, head_b, nullptr, 0, 1.0f);
}

// round 3
// speedup vs baseline: 2.2631x; 1.0094x over previous
#include <cuda_runtime.h>
#include <cstdint>

#define Bq 2
#define Tq 1024
#define Eq 1024
#define Hq 16
#define Dq 64
#define Lq 6
#define FFq 4096
#define Vq 32000

// ---------------- scratch (device globals; no runtime allocation) ----------
__device__ float g_x [Bq*Tq*Eq];
__device__ float g_h [Bq*Tq*Eq];
__device__ float g_q [Bq*Tq*Eq];
__device__ float g_k [Bq*Tq*Eq];
__device__ float g_v [Bq*Tq*Eq];
__device__ float g_o [Bq*Tq*Eq];
__device__ float g_ff[Bq*Tq*FFq];
__device__ float g_att[(size_t)Bq*Hq*Tq*Tq];

// ---------------- block reductions (256 threads) ----------------------------
__device__ __forceinline__ float block_reduce_sum(float v) {
    __shared__ float sh[8];
    #pragma unroll
    for (int o = 16; o > 0; o >>= 1) v += __shfl_xor_sync(0xffffffffu, v, o);
    int lane = threadIdx.x & 31, w = threadIdx.x >> 5;
    if (lane == 0) sh[w] = v;
    __syncthreads();
    float r = (lane < 8) ? sh[lane] : 0.f;
    #pragma unroll
    for (int o = 4; o > 0; o >>= 1) r += __shfl_xor_sync(0xffffffffu, r, o);
    r = __shfl_sync(0xffffffffu, r, 0);
    __syncthreads();
    return r;
}

__device__ __forceinline__ float block_reduce_max(float v) {
    __shared__ float sh[8];
    #pragma unroll
    for (int o = 16; o > 0; o >>= 1) v = fmaxf(v, __shfl_xor_sync(0xffffffffu, v, o));
    int lane = threadIdx.x & 31, w = threadIdx.x >> 5;
    if (lane == 0) sh[w] = v;
    __syncthreads();
    float r = (lane < 8) ? sh[lane] : -1e30f;
    #pragma unroll
    for (int o = 4; o > 0; o >>= 1) r = fmaxf(r, __shfl_xor_sync(0xffffffffu, r, o));
    r = __shfl_sync(0xffffffffu, r, 0);
    __syncthreads();
    return r;
}

// ---------------- embedding --------------------------------------------------
__global__ __launch_bounds__(256) void embed_kernel(
    const int* __restrict__ idx, const float* __restrict__ tok_w,
    const float* __restrict__ pos, float* __restrict__ x)
{
    int i = blockIdx.x * 256 + threadIdx.x;          // over B*T*E/4 float4s
    const int E4 = Eq / 4;
    int e4 = i % E4;
    int bt = i / E4;
    int t  = bt % Tq;
    int tok = idx[bt];
    float4 tw = ((const float4*)tok_w)[(int64_t)tok * E4 + e4];
    float4 pe = ((const float4*)pos)[(int64_t)t * E4 + e4];
    ((float4*)x)[i] = make_float4(tw.x + pe.x, tw.y + pe.y, tw.z + pe.z, tw.w + pe.w);
}

// ---------------- layernorm (one block per row of E=1024) -------------------
__global__ __launch_bounds__(256) void ln_kernel(
    const float* __restrict__ x, float* __restrict__ y,
    const float* __restrict__ s, const float* __restrict__ b)
{
    int row = blockIdx.x;
    int tid = threadIdx.x;
    const float4* xr = (const float4*)(x + (int64_t)row * Eq);
    float4 v = xr[tid];
    float tot = block_reduce_sum(v.x + v.y + v.z + v.w);
    float mean = tot * (1.f / Eq);
    float dx = v.x - mean, dy = v.y - mean, dz = v.z - mean, dw = v.w - mean;
    float tot2 = block_reduce_sum(dx*dx + dy*dy + dz*dz + dw*dw);
    float inv = rsqrtf(tot2 * (1.f / Eq) + 1e-5f);
    float4 sv = ((const float4*)s)[tid];
    float4 bv = ((const float4*)b)[tid];
    float4 o;
    o.x = dx * inv * sv.x + bv.x;
    o.y = dy * inv * sv.y + bv.y;
    o.z = dz * inv * sv.z + bv.z;
    o.w = dw * inv * sv.w + bv.w;
    ((float4*)(y + (int64_t)row * Eq))[tid] = o;
}

// ---------------- causal softmax (one block per attention row) --------------
__global__ __launch_bounds__(256) void softmax_causal(float* __restrict__ att)
{
    int r = blockIdx.x;              // 0 .. B*H*T-1
    int t = r % Tq;
    float* row = att + (int64_t)r * Tq;
    int tid = threadIdx.x;
    int c0 = tid * 4;
    float4 v = ((const float4*)row)[tid];
    float vals[4] = {v.x, v.y, v.z, v.w};
    float m = -1e30f;
    #pragma unroll
    for (int i = 0; i < 4; i++) if (c0 + i <= t) m = fmaxf(m, vals[i]);
    float mx = block_reduce_max(m);
    float e[4]; float s = 0.f;
    #pragma unroll
    for (int i = 0; i < 4; i++) {
        e[i] = (c0 + i <= t) ? __expf(vals[i] - mx) : 0.f;
        s += e[i];
    }
    float tot = block_reduce_sum(s);
    float inv = 1.f / tot;
    ((float4*)row)[tid] = make_float4(e[0]*inv, e[1]*inv, e[2]*inv, e[3]*inv);
}

// ---------------- tf32 helpers -----------------------------------------------
__device__ __forceinline__ uint32_t f2tf(float f) {
    uint32_t u;
    asm("cvt.rna.tf32.f32 %0, %1;" : "=r"(u) : "f"(f));
    return u;
}

#define MMA_TF32(c, a, b)                                                     \
    asm volatile(                                                             \
        "mma.sync.aligned.m16n8k8.row.col.f32.tf32.tf32.f32 "                 \
        "{%0,%1,%2,%3}, {%4,%5,%6,%7}, {%8,%9}, {%0,%1,%2,%3};"               \
        : "+f"(c[0]), "+f"(c[1]), "+f"(c[2]), "+f"(c[3])                      \
        : "r"(a[0]), "r"(a[1]), "r"(a[2]), "r"(a[3]), "r"(b[0]), "r"(b[1]))

// ---------------- TF32 tensor-core GEMM --------------------------------------
// C = alpha * A @ B (+bias[n]) (+resid) (ReLU optional)
// A: M x K row-major (lda). B: !TB -> K x N row-major (ldb); TB -> (k,n) at n*ldb+k.
// Block tile BM x 128 x 16, 8 warps, double-buffered smem, reg-staged prefetch.
// Optional alt operands B1/C1, B2/C2 selected by zo (for fused QKV).
// causal: 0 none; 1 = skip tiles fully above diagonal (scores); 2 = truncate K
//         to row0+BM (att@V, excluded A entries are exact zeros).
template<int BM, bool TB>
__global__ __launch_bounds__(256, 2) void gemm_tc(
    const float* __restrict__ A, const float* __restrict__ Bm, float* __restrict__ C,
    int M, int N, int K, int lda, int ldb, int ldc,
    int batch_inner,
    long long sAi, long long sAo, long long sBi, long long sBo,
    long long sCi, long long sCo,
    const float* __restrict__ bias, const float* __restrict__ resid,
    int relu, float alpha,
    const float* B1, float* C1, const float* B2, float* C2,
    int causal)
{
    constexpr int II = BM / 32;        // i-tiles per warp
    __shared__ uint32_t As[2][16][BM + 4];
    __shared__ uint32_t Bs[2][16][132];

    int zi = blockIdx.z % batch_inner;
    int zo = blockIdx.z / batch_inner;
    if (B1 && zo == 1) { Bm = B1; C = C1; }
    if (B2 && zo == 2) { Bm = B2; C = C2; }
    A  += (int64_t)zi * sAi + (int64_t)zo * sAo;
    Bm += (int64_t)zi * sBi + (int64_t)zo * sBo;
    int64_t cbase = (int64_t)zi * sCi + (int64_t)zo * sCo;

    int row0 = blockIdx.y * BM;
    int col0 = blockIdx.x * 128;

    if (causal == 1 && col0 > row0 + BM - 1) return;   // fully masked tile
    int Keff = (causal == 2) ? min(K, row0 + BM) : K;

    int tid  = threadIdx.x;
    int warp = tid >> 5, lane = tid & 31;
    int g = lane >> 2, t = lane & 3;
    int wM = (warp & 1) * (BM / 2);
    int wN = (warp >> 1) * 32;

    float acc[II][4][4];
    #pragma unroll
    for (int i = 0; i < II; i++)
        #pragma unroll
        for (int j = 0; j < 4; j++)
            #pragma unroll
            for (int e = 0; e < 4; e++) acc[i][j][e] = 0.f;

    const int aM  = tid >> 2;    // 0..63
    const int akq = tid & 3;     // 0..3
    constexpr int AIT = BM / 64; // A-load iterations

    float4 stA[AIT > 0 ? AIT : 1], stB[2];

    auto loadg = [&](int k0) {
        #pragma unroll
        for (int it = 0; it < AIT; it++) {
            int m = aM + it * 64;
            float4 v = make_float4(0.f, 0.f, 0.f, 0.f);
            if (row0 + m < M)
                v = *(const float4*)(A + (int64_t)(row0 + m) * lda + k0 + akq * 4);
            stA[it] = v;
        }
        #pragma unroll
        for (int it = 0; it < 2; it++) {
            float4 v = make_float4(0.f, 0.f, 0.f, 0.f);
            if (!TB) {
                int n4 = tid & 31;
                int kk = (tid >> 5) + it * 8;
                int n  = col0 + n4 * 4;
                if (n + 3 < N)
                    v = *(const float4*)(Bm + (int64_t)(k0 + kk) * ldb + n);
            } else {
                int n = (tid >> 2) + it * 64;
                if (col0 + n < N)
                    v = *(const float4*)(Bm + (int64_t)(col0 + n) * ldb + k0 + akq * 4);
            }
            stB[it] = v;
        }
    };

    auto stores = [&](int buf) {
        #pragma unroll
        for (int it = 0; it < AIT; it++) {
            int m = aM + it * 64;
            As[buf][akq * 4 + 0][m] = f2tf(stA[it].x);
            As[buf][akq * 4 + 1][m] = f2tf(stA[it].y);
            As[buf][akq * 4 + 2][m] = f2tf(stA[it].z);
            As[buf][akq * 4 + 3][m] = f2tf(stA[it].w);
        }
        #pragma unroll
        for (int it = 0; it < 2; it++) {
            if (!TB) {
                int n4 = tid & 31;
                int kk = (tid >> 5) + it * 8;
                Bs[buf][kk][n4 * 4 + 0] = f2tf(stB[it].x);
                Bs[buf][kk][n4 * 4 + 1] = f2tf(stB[it].y);
                Bs[buf][kk][n4 * 4 + 2] = f2tf(stB[it].z);
                Bs[buf][kk][n4 * 4 + 3] = f2tf(stB[it].w);
            } else {
                int n = (tid >> 2) + it * 64;
                Bs[buf][akq * 4 + 0][n] = f2tf(stB[it].x);
                Bs[buf][akq * 4 + 1][n] = f2tf(stB[it].y);
                Bs[buf][akq * 4 + 2][n] = f2tf(stB[it].z);
                Bs[buf][akq * 4 + 3][n] = f2tf(stB[it].w);
            }
        }
    };

    auto compute = [&](int buf) {
        #pragma unroll
        for (int ks = 0; ks < 2; ks++) {
            int kb = ks * 8;
            uint32_t af[II][4], bf[4][2];
            #pragma unroll
            for (int i = 0; i < II; i++) {
                int m = wM + i * 16 + g;
                af[i][0] = As[buf][kb + t][m];
                af[i][1] = As[buf][kb + t][m + 8];
                af[i][2] = As[buf][kb + t + 4][m];
                af[i][3] = As[buf][kb + t + 4][m + 8];
            }
            #pragma unroll
            for (int j = 0; j < 4; j++) {
                int n = wN + j * 8 + g;
                bf[j][0] = Bs[buf][kb + t][n];
                bf[j][1] = Bs[buf][kb + t + 4][n];
            }
            #pragma unroll
            for (int i = 0; i < II; i++)
                #pragma unroll
                for (int j = 0; j < 4; j++)
                    MMA_TF32(acc[i][j], af[i], bf[j]);
        }
    };

    // pipeline: prologue
    loadg(0);
    stores(0);
    __syncthreads();

    int nit = Keff >> 4;
    int buf = 0;
    for (int itk = 1; itk < nit; itk++) {
        loadg(itk << 4);
        compute(buf);
        stores(buf ^ 1);
        __syncthreads();
        buf ^= 1;
    }
    compute(buf);

    // ---- epilogue ----
    float* Cp = C + cbase;
    const float* Rp = resid ? (resid + cbase) : nullptr;
    #pragma unroll
    for (int i = 0; i < II; i++) {
        int r0 = row0 + wM + i * 16 + g;
        #pragma unroll
        for (int j = 0; j < 4; j++) {
            int c = col0 + wN + j * 8 + t * 2;
            if (c >= N) continue;
            #pragma unroll
            for (int half = 0; half < 2; half++) {
                int r = r0 + half * 8;
                if (r >= M) continue;
                float v0 = alpha * acc[i][j][half * 2 + 0];
                float v1 = alpha * acc[i][j][half * 2 + 1];
                if (bias) { v0 += bias[c]; v1 += bias[c + 1]; }
                if (Rp) {
                    float2 rv = *(const float2*)(Rp + (int64_t)r * ldc + c);
                    v0 += rv.x; v1 += rv.y;
                }
                if (relu) { v0 = fmaxf(v0, 0.f); v1 = fmaxf(v1, 0.f); }
                *(float2*)(Cp + (int64_t)r * ldc + c) = make_float2(v0, v1);
            }
        }
    }
}

// ---------------- host orchestration ----------------------------------------
static inline dim3 ggrid(int M, int N, int batch, int bm) {
    return dim3((unsigned)((N + 127) / 128), (unsigned)((M + bm - 1) / bm), (unsigned)batch);
}

extern "C" void kernel_launch(void* const* d_in, const int* in_sizes, int n_in,
                              void* d_out, int out_size)
{
    const int*   idx    = (const int*)  d_in[0];
    const float* tok_w  = (const float*)d_in[1];
    const float* pos    = (const float*)d_in[2];
    const float* ln1_s  = (const float*)d_in[3];
    const float* ln1_b  = (const float*)d_in[4];
    const float* wq     = (const float*)d_in[5];
    const float* wk     = (const float*)d_in[6];
    const float* wv     = (const float*)d_in[7];
    const float* wo     = (const float*)d_in[8];
    const float* bo     = (const float*)d_in[9];
    const float* ln2_s  = (const float*)d_in[10];
    const float* ln2_b  = (const float*)d_in[11];
    const float* w1     = (const float*)d_in[12];
    const float* b1     = (const float*)d_in[13];
    const float* w2     = (const float*)d_in[14];
    const float* b2     = (const float*)d_in[15];
    const float* lnf_s  = (const float*)d_in[16];
    const float* lnf_b  = (const float*)d_in[17];
    const float* head_w = (const float*)d_in[18];
    const float* head_b = (const float*)d_in[19];
    float* out = (float*)d_out;

    float *x, *h, *q, *k, *v, *o, *ff, *att;
    cudaGetSymbolAddress((void**)&x,   g_x);
    cudaGetSymbolAddress((void**)&h,   g_h);
    cudaGetSymbolAddress((void**)&q,   g_q);
    cudaGetSymbolAddress((void**)&k,   g_k);
    cudaGetSymbolAddress((void**)&v,   g_v);
    cudaGetSymbolAddress((void**)&o,   g_o);
    cudaGetSymbolAddress((void**)&ff,  g_ff);
    cudaGetSymbolAddress((void**)&att, g_att);

    const int M = Bq * Tq;                  // 2048
    const float scale = 0.125f;             // 1/sqrt(64)

    // embedding
    embed_kernel<<<(M * Eq / 4 + 255) / 256, 256>>>(idx, tok_w, pos, x);

    for (int l = 0; l < Lq; l++) {
        const float* Wq = wq + (int64_t)l * Eq * Eq;
        const float* Wk = wk + (int64_t)l * Eq * Eq;
        const float* Wv = wv + (int64_t)l * Eq * Eq;
        const float* Wo = wo + (int64_t)l * Eq * Eq;
        const float* W1 = w1 + (int64_t)l * Eq * FFq;
        const float* W2 = w2 + (int64_t)l * FFq * Eq;

        // ln1
        ln_kernel<<<M, 256>>>(x, h, ln1_s + l * Eq, ln1_b + l * Eq);

        // fused q/k/v projections (z selects weight + output)
        gemm_tc<128, false><<<ggrid(M, Eq, 3, 128), 256>>>(h, Wq, q,
            M, Eq, Eq, Eq, Eq, Eq,
            1, 0,0,0,0,0,0, nullptr, nullptr, 0, 1.0f,
            Wk, k, Wv, v, 0);

        // scores: att[b,h,t,s] = scale * q . k  (batched over B*H, B^T form)
        gemm_tc<128, true><<<ggrid(Tq, Tq, Bq * Hq, 128), 256>>>(q, k, att,
            Tq, Tq, Dq, Eq, Eq, Tq,
            Hq,
            /*sAi*/ Dq, /*sAo*/ (long long)Tq * Eq,
            /*sBi*/ Dq, /*sBo*/ (long long)Tq * Eq,
            /*sCi*/ (long long)Tq * Tq, /*sCo*/ (long long)Hq * Tq * Tq,
            nullptr, nullptr, 0, scale,
            nullptr, nullptr, nullptr, nullptr, 1);

        // causal softmax
        softmax_causal<<<Bq * Hq * Tq, 256>>>(att);

        // o = att @ v  (batched over B*H), K truncated past the diagonal
        gemm_tc<64, false><<<ggrid(Tq, Dq, Bq * Hq, 64), 256>>>(att, v, o,
            Tq, Dq, Tq, Tq, Eq, Eq,
            Hq,
            /*sAi*/ (long long)Tq * Tq, /*sAo*/ (long long)Hq * Tq * Tq,
            /*sBi*/ Dq, /*sBo*/ (long long)Tq * Eq,
            /*sCi*/ Dq, /*sCo*/ (long long)Tq * Eq,
            nullptr, nullptr, 0, 1.0f,
            nullptr, nullptr, nullptr, nullptr, 2);

        // x = x + o @ Wo + bo
        gemm_tc<64, false><<<ggrid(M, Eq, 1, 64), 256>>>(o, Wo, x,
            M, Eq, Eq, Eq, Eq, Eq,
            1, 0,0,0,0,0,0, bo + l * Eq, x, 0, 1.0f,
            nullptr, nullptr, nullptr, nullptr, 0);

        // ln2
        ln_kernel<<<M, 256>>>(x, h, ln2_s + l * Eq, ln2_b + l * Eq);

        // ff = relu(h @ W1 + b1)
        gemm_tc<128, false><<<ggrid(M, FFq, 1, 128), 256>>>(h, W1, ff,
            M, FFq, Eq, Eq, FFq, FFq,
            1, 0,0,0,0,0,0, b1 + l * FFq, nullptr, 1, 1.0f,
            nullptr, nullptr, nullptr, nullptr, 0);

        // x = x + ff @ W2 + b2
        gemm_tc<64, false><<<ggrid(M, Eq, 1, 64), 256>>>(ff, W2, x,
            M, Eq, FFq, FFq, Eq, Eq,
            1, 0,0,0,0,0,0, b2 + l * Eq, x, 0, 1.0f,
            nullptr, nullptr, nullptr, nullptr, 0);
    }

    // final layernorm
    ln_kernel<<<M, 256>>>(x, h, lnf_s, lnf_b);

    // logits = h @ head_w + head_b
    gemm_tc<128, false><<<ggrid(M, Vq, 1, 128), 256>>>(h, head_w, out,
        M, Vq, Eq, Eq, Vq, Vq,
        1, 0,0,0,0,0,0, head_b, nullptr, 0, 1.0f,
        nullptr, nullptr, nullptr, nullptr, 0);
}

// round 4
// speedup vs baseline: 2.5225x; 1.1146x over previous
#include <cuda_runtime.h>
#include <cstdint>

#define Bq 2
#define Tq 1024
#define Eq 1024
#define Hq 16
#define Dq 64
#define Lq 6
#define FFq 4096
#define Vq 32000

// ---------------- scratch (device globals; no runtime allocation) ----------
__device__ float g_x [Bq*Tq*Eq];
__device__ float g_h [Bq*Tq*Eq];
__device__ float g_q [Bq*Tq*Eq];
__device__ float g_k [Bq*Tq*Eq];
__device__ float g_v [Bq*Tq*Eq];
__device__ float g_o [Bq*Tq*Eq];
__device__ float g_ff[Bq*Tq*FFq];

// ---------------- block reductions (256 threads) ----------------------------
__device__ __forceinline__ float block_reduce_sum(float v) {
    __shared__ float sh[8];
    #pragma unroll
    for (int o = 16; o > 0; o >>= 1) v += __shfl_xor_sync(0xffffffffu, v, o);
    int lane = threadIdx.x & 31, w = threadIdx.x >> 5;
    if (lane == 0) sh[w] = v;
    __syncthreads();
    float r = (lane < 8) ? sh[lane] : 0.f;
    #pragma unroll
    for (int o = 4; o > 0; o >>= 1) r += __shfl_xor_sync(0xffffffffu, r, o);
    r = __shfl_sync(0xffffffffu, r, 0);
    __syncthreads();
    return r;
}

// ---------------- embedding --------------------------------------------------
__global__ __launch_bounds__(256) void embed_kernel(
    const int* __restrict__ idx, const float* __restrict__ tok_w,
    const float* __restrict__ pos, float* __restrict__ x)
{
    int i = blockIdx.x * 256 + threadIdx.x;          // over B*T*E/4 float4s
    const int E4 = Eq / 4;
    int e4 = i % E4;
    int bt = i / E4;
    int t  = bt % Tq;
    int tok = idx[bt];
    float4 tw = ((const float4*)tok_w)[(int64_t)tok * E4 + e4];
    float4 pe = ((const float4*)pos)[(int64_t)t * E4 + e4];
    ((float4*)x)[i] = make_float4(tw.x + pe.x, tw.y + pe.y, tw.z + pe.z, tw.w + pe.w);
}

// ---------------- layernorm (one block per row of E=1024) -------------------
__global__ __launch_bounds__(256) void ln_kernel(
    const float* __restrict__ x, float* __restrict__ y,
    const float* __restrict__ s, const float* __restrict__ b)
{
    int row = blockIdx.x;
    int tid = threadIdx.x;
    const float4* xr = (const float4*)(x + (int64_t)row * Eq);
    float4 v = xr[tid];
    float tot = block_reduce_sum(v.x + v.y + v.z + v.w);
    float mean = tot * (1.f / Eq);
    float dx = v.x - mean, dy = v.y - mean, dz = v.z - mean, dw = v.w - mean;
    float tot2 = block_reduce_sum(dx*dx + dy*dy + dz*dz + dw*dw);
    float inv = rsqrtf(tot2 * (1.f / Eq) + 1e-5f);
    float4 sv = ((const float4*)s)[tid];
    float4 bv = ((const float4*)b)[tid];
    float4 o;
    o.x = dx * inv * sv.x + bv.x;
    o.y = dy * inv * sv.y + bv.y;
    o.z = dz * inv * sv.z + bv.z;
    o.w = dw * inv * sv.w + bv.w;
    ((float4*)(y + (int64_t)row * Eq))[tid] = o;
}

// ---------------- tf32 helpers -----------------------------------------------
__device__ __forceinline__ uint32_t f2tf(float f) {
    uint32_t u;
    asm("cvt.rna.tf32.f32 %0, %1;" : "=r"(u) : "f"(f));
    return u;
}

#define MMA_TF32(c, a, b)                                                     \
    asm volatile(                                                             \
        "mma.sync.aligned.m16n8k8.row.col.f32.tf32.tf32.f32 "                 \
        "{%0,%1,%2,%3}, {%4,%5,%6,%7}, {%8,%9}, {%0,%1,%2,%3};"               \
        : "+f"(c[0]), "+f"(c[1]), "+f"(c[2]), "+f"(c[3])                      \
        : "r"(a[0]), "r"(a[1]), "r"(a[2]), "r"(a[3]), "r"(b[0]), "r"(b[1]))

// ---------------- flash attention (causal, D=64) -----------------------------
// One block = one (b, h, 128-row q tile). 256 threads = 8 warps, each warp
// owns a 16-row slab. S kept in registers; online softmax; P staged via smem
// as tf32; O accumulated in fp32 registers. Never materializes T x T.
// Dynamic smem layout (uint32 words):
//   Qs [64][132]   tf32, k-major      (8448 w)
//   Ks [64][132]   tf32, k-major      (8448 w)
//   Vs [128][68]   tf32, row-major    (8704 w)
//   Ps [128][132]  tf32, k-major      (16896 w)
#define FL_SMEM_WORDS (8448 + 8448 + 8704 + 16896)

__global__ void __launch_bounds__(256, 1) flash_kernel(
    const float* __restrict__ q, const float* __restrict__ k,
    const float* __restrict__ v, float* __restrict__ o)
{
    extern __shared__ uint32_t dsm[];
    uint32_t* Qs = dsm;             // [64][132]
    uint32_t* Ks = Qs + 8448;       // [64][132]
    uint32_t* Vs = Ks + 8448;       // [128][68]
    uint32_t* Ps = Vs + 8704;       // [128][132]

    int bh = blockIdx.y;
    int b  = bh >> 4, hh = bh & 15;
    int qi = (int)gridDim.x - 1 - blockIdx.x;   // heavy tiles first
    int q0 = qi * 128;

    const float* qbase = q + (int64_t)b * Tq * Eq + hh * Dq;
    const float* kbase = k + (int64_t)b * Tq * Eq + hh * Dq;
    const float* vbase = v + (int64_t)b * Tq * Eq + hh * Dq;
    float*       obase = o + (int64_t)b * Tq * Eq + hh * Dq;

    int tid = threadIdx.x, warp = tid >> 5, lane = tid & 31;
    int g = lane >> 2, t = lane & 3;
    int m0 = warp * 16;

    // ---- load Q tile (once) ----
    {
        int mrow = tid >> 4;
        int d4   = (tid & 15) * 4;
        #pragma unroll
        for (int it = 0; it < 8; it++) {
            int m = mrow + it * 16;
            float4 qv = *(const float4*)(qbase + (int64_t)(q0 + m) * Eq + d4);
            Qs[(d4 + 0) * 132 + m] = f2tf(qv.x);
            Qs[(d4 + 1) * 132 + m] = f2tf(qv.y);
            Qs[(d4 + 2) * 132 + m] = f2tf(qv.z);
            Qs[(d4 + 3) * 132 + m] = f2tf(qv.w);
        }
    }

    float m_run0 = -1e30f, m_run1 = -1e30f;
    float l_run0 = 0.f,    l_run1 = 0.f;
    float oacc[8][4];
    #pragma unroll
    for (int nj = 0; nj < 8; nj++)
        #pragma unroll
        for (int e = 0; e < 4; e++) oacc[nj][e] = 0.f;

    int r0 = q0 + m0 + g, r1 = r0 + 8;

    for (int jt = 0; jt <= qi; jt++) {
        int kv0 = jt * 128;
        __syncthreads();
        // ---- load K, V tiles ----
        {
            int nrow = tid >> 4;
            int d4   = (tid & 15) * 4;
            #pragma unroll
            for (int it = 0; it < 8; it++) {
                int n = nrow + it * 16;
                float4 kv_ = *(const float4*)(kbase + (int64_t)(kv0 + n) * Eq + d4);
                Ks[(d4 + 0) * 132 + n] = f2tf(kv_.x);
                Ks[(d4 + 1) * 132 + n] = f2tf(kv_.y);
                Ks[(d4 + 2) * 132 + n] = f2tf(kv_.z);
                Ks[(d4 + 3) * 132 + n] = f2tf(kv_.w);
                float4 vv = *(const float4*)(vbase + (int64_t)(kv0 + n) * Eq + d4);
                Vs[n * 68 + d4 + 0] = f2tf(vv.x);
                Vs[n * 68 + d4 + 1] = f2tf(vv.y);
                Vs[n * 68 + d4 + 2] = f2tf(vv.z);
                Vs[n * 68 + d4 + 3] = f2tf(vv.w);
            }
        }
        __syncthreads();

        // ---- S = Q @ K^T for this warp's 16-row slab (16 x 128) ----
        float sacc[16][4];
        #pragma unroll
        for (int j = 0; j < 16; j++)
            #pragma unroll
            for (int e = 0; e < 4; e++) sacc[j][e] = 0.f;

        #pragma unroll
        for (int kb = 0; kb < 8; kb++) {
            uint32_t af[4];
            af[0] = Qs[(kb * 8 + t    ) * 132 + m0 + g];
            af[1] = Qs[(kb * 8 + t    ) * 132 + m0 + g + 8];
            af[2] = Qs[(kb * 8 + t + 4) * 132 + m0 + g];
            af[3] = Qs[(kb * 8 + t + 4) * 132 + m0 + g + 8];
            #pragma unroll
            for (int j = 0; j < 16; j++) {
                uint32_t bf[2];
                bf[0] = Ks[(kb * 8 + t    ) * 132 + j * 8 + g];
                bf[1] = Ks[(kb * 8 + t + 4) * 132 + j * 8 + g];
                MMA_TF32(sacc[j], af, bf);
            }
        }

        // ---- scale + causal mask + row max ----
        float mx0 = -1e30f, mx1 = -1e30f;
        #pragma unroll
        for (int j = 0; j < 16; j++) {
            #pragma unroll
            for (int e = 0; e < 2; e++) {
                int c = kv0 + j * 8 + t * 2 + e;
                float s0 = sacc[j][e]     * 0.125f;
                float s1 = sacc[j][e + 2] * 0.125f;
                if (c > r0) s0 = -1e30f;
                if (c > r1) s1 = -1e30f;
                sacc[j][e]     = s0;
                sacc[j][e + 2] = s1;
                mx0 = fmaxf(mx0, s0);
                mx1 = fmaxf(mx1, s1);
            }
        }
        mx0 = fmaxf(mx0, __shfl_xor_sync(0xffffffffu, mx0, 1));
        mx0 = fmaxf(mx0, __shfl_xor_sync(0xffffffffu, mx0, 2));
        mx1 = fmaxf(mx1, __shfl_xor_sync(0xffffffffu, mx1, 1));
        mx1 = fmaxf(mx1, __shfl_xor_sync(0xffffffffu, mx1, 2));

        float mnew0 = fmaxf(m_run0, mx0);
        float mnew1 = fmaxf(m_run1, mx1);
        float f0 = __expf(m_run0 - mnew0);
        float f1 = __expf(m_run1 - mnew1);

        // ---- P = exp(S - m), write to smem (tf32), row sums ----
        float sum0 = 0.f, sum1 = 0.f;
        #pragma unroll
        for (int j = 0; j < 16; j++) {
            #pragma unroll
            for (int e = 0; e < 2; e++) {
                float p0 = __expf(sacc[j][e]     - mnew0);
                float p1 = __expf(sacc[j][e + 2] - mnew1);
                sum0 += p0;
                sum1 += p1;
                int krow = j * 8 + t * 2 + e;
                Ps[krow * 132 + m0 + g]     = f2tf(p0);
                Ps[krow * 132 + m0 + g + 8] = f2tf(p1);
            }
        }
        sum0 += __shfl_xor_sync(0xffffffffu, sum0, 1);
        sum0 += __shfl_xor_sync(0xffffffffu, sum0, 2);
        sum1 += __shfl_xor_sync(0xffffffffu, sum1, 1);
        sum1 += __shfl_xor_sync(0xffffffffu, sum1, 2);

        l_run0 = l_run0 * f0 + sum0;
        l_run1 = l_run1 * f1 + sum1;
        m_run0 = mnew0;
        m_run1 = mnew1;

        // ---- rescale O accumulator ----
        #pragma unroll
        for (int nj = 0; nj < 8; nj++) {
            oacc[nj][0] *= f0; oacc[nj][1] *= f0;
            oacc[nj][2] *= f1; oacc[nj][3] *= f1;
        }
        __syncwarp();

        // ---- O += P @ V  (K-dim = 128) ----
        #pragma unroll
        for (int kb = 0; kb < 16; kb++) {
            uint32_t af[4];
            af[0] = Ps[(kb * 8 + t    ) * 132 + m0 + g];
            af[1] = Ps[(kb * 8 + t    ) * 132 + m0 + g + 8];
            af[2] = Ps[(kb * 8 + t + 4) * 132 + m0 + g];
            af[3] = Ps[(kb * 8 + t + 4) * 132 + m0 + g + 8];
            #pragma unroll
            for (int nj = 0; nj < 8; nj++) {
                uint32_t bf[2];
                bf[0] = Vs[(kb * 8 + t    ) * 68 + nj * 8 + g];
                bf[1] = Vs[(kb * 8 + t + 4) * 68 + nj * 8 + g];
                MMA_TF32(oacc[nj], af, bf);
            }
        }
    }

    // ---- epilogue: normalize and store ----
    float inv0 = 1.f / l_run0;
    float inv1 = 1.f / l_run1;
    #pragma unroll
    for (int nj = 0; nj < 8; nj++) {
        int c = nj * 8 + t * 2;
        *(float2*)(obase + (int64_t)r0 * Eq + c) =
            make_float2(oacc[nj][0] * inv0, oacc[nj][1] * inv0);
        *(float2*)(obase + (int64_t)r1 * Eq + c) =
            make_float2(oacc[nj][2] * inv1, oacc[nj][3] * inv1);
    }
}

// ---------------- TF32 tensor-core GEMM --------------------------------------
// C = alpha * A @ B (+bias[n]) (+resid) (ReLU optional)
// A: M x K row-major (lda). B: K x N row-major (ldb).
// Block tile BM x 128 x 16, 8 warps, double-buffered smem, reg-staged prefetch.
// Optional alt operands B1/C1, B2/C2 selected by zo (for fused QKV).
template<int BM>
__global__ __launch_bounds__(256, 2) void gemm_tc(
    const float* __restrict__ A, const float* __restrict__ Bm, float* __restrict__ C,
    int M, int N, int K, int lda, int ldb, int ldc,
    const float* __restrict__ bias, const float* __restrict__ resid,
    int relu, float alpha,
    const float* B1, float* C1, const float* B2, float* C2)
{
    constexpr int II = BM / 32;        // i-tiles per warp
    __shared__ uint32_t As[2][16][BM + 4];
    __shared__ uint32_t Bs[2][16][132];

    int zo = blockIdx.z;
    if (B1 && zo == 1) { Bm = B1; C = C1; }
    if (B2 && zo == 2) { Bm = B2; C = C2; }

    int row0 = blockIdx.y * BM;
    int col0 = blockIdx.x * 128;

    int tid  = threadIdx.x;
    int warp = tid >> 5, lane = tid & 31;
    int g = lane >> 2, t = lane & 3;
    int wM = (warp & 1) * (BM / 2);
    int wN = (warp >> 1) * 32;

    float acc[II][4][4];
    #pragma unroll
    for (int i = 0; i < II; i++)
        #pragma unroll
        for (int j = 0; j < 4; j++)
            #pragma unroll
            for (int e = 0; e < 4; e++) acc[i][j][e] = 0.f;

    const int aM  = tid >> 2;    // 0..63
    const int akq = tid & 3;     // 0..3
    constexpr int AIT = BM / 64; // A-load iterations

    float4 stA[AIT > 0 ? AIT : 1], stB[2];

    auto loadg = [&](int k0) {
        #pragma unroll
        for (int it = 0; it < AIT; it++) {
            int m = aM + it * 64;
            float4 v = make_float4(0.f, 0.f, 0.f, 0.f);
            if (row0 + m < M)
                v = *(const float4*)(A + (int64_t)(row0 + m) * lda + k0 + akq * 4);
            stA[it] = v;
        }
        #pragma unroll
        for (int it = 0; it < 2; it++) {
            float4 v = make_float4(0.f, 0.f, 0.f, 0.f);
            int n4 = tid & 31;
            int kk = (tid >> 5) + it * 8;
            int n  = col0 + n4 * 4;
            if (n + 3 < N)
                v = *(const float4*)(Bm + (int64_t)(k0 + kk) * ldb + n);
            stB[it] = v;
        }
    };

    auto stores = [&](int buf) {
        #pragma unroll
        for (int it = 0; it < AIT; it++) {
            int m = aM + it * 64;
            As[buf][akq * 4 + 0][m] = f2tf(stA[it].x);
            As[buf][akq * 4 + 1][m] = f2tf(stA[it].y);
            As[buf][akq * 4 + 2][m] = f2tf(stA[it].z);
            As[buf][akq * 4 + 3][m] = f2tf(stA[it].w);
        }
        #pragma unroll
        for (int it = 0; it < 2; it++) {
            int n4 = tid & 31;
            int kk = (tid >> 5) + it * 8;
            Bs[buf][kk][n4 * 4 + 0] = f2tf(stB[it].x);
            Bs[buf][kk][n4 * 4 + 1] = f2tf(stB[it].y);
            Bs[buf][kk][n4 * 4 + 2] = f2tf(stB[it].z);
            Bs[buf][kk][n4 * 4 + 3] = f2tf(stB[it].w);
        }
    };

    auto compute = [&](int buf) {
        #pragma unroll
        for (int ks = 0; ks < 2; ks++) {
            int kb = ks * 8;
            uint32_t af[II][4], bf[4][2];
            #pragma unroll
            for (int i = 0; i < II; i++) {
                int m = wM + i * 16 + g;
                af[i][0] = As[buf][kb + t][m];
                af[i][1] = As[buf][kb + t][m + 8];
                af[i][2] = As[buf][kb + t + 4][m];
                af[i][3] = As[buf][kb + t + 4][m + 8];
            }
            #pragma unroll
            for (int j = 0; j < 4; j++) {
                int n = wN + j * 8 + g;
                bf[j][0] = Bs[buf][kb + t][n];
                bf[j][1] = Bs[buf][kb + t + 4][n];
            }
            #pragma unroll
            for (int i = 0; i < II; i++)
                #pragma unroll
                for (int j = 0; j < 4; j++)
                    MMA_TF32(acc[i][j], af[i], bf[j]);
        }
    };

    // pipeline: prologue
    loadg(0);
    stores(0);
    __syncthreads();

    int nit = K >> 4;
    int buf = 0;
    for (int itk = 1; itk < nit; itk++) {
        loadg(itk << 4);
        compute(buf);
        stores(buf ^ 1);
        __syncthreads();
        buf ^= 1;
    }
    compute(buf);

    // ---- epilogue ----
    #pragma unroll
    for (int i = 0; i < II; i++) {
        int r0 = row0 + wM + i * 16 + g;
        #pragma unroll
        for (int j = 0; j < 4; j++) {
            int c = col0 + wN + j * 8 + t * 2;
            if (c >= N) continue;
            #pragma unroll
            for (int half = 0; half < 2; half++) {
                int r = r0 + half * 8;
                if (r >= M) continue;
                float v0 = alpha * acc[i][j][half * 2 + 0];
                float v1 = alpha * acc[i][j][half * 2 + 1];
                if (bias) { v0 += bias[c]; v1 += bias[c + 1]; }
                if (resid) {
                    float2 rv = *(const float2*)(resid + (int64_t)r * ldc + c);
                    v0 += rv.x; v1 += rv.y;
                }
                if (relu) { v0 = fmaxf(v0, 0.f); v1 = fmaxf(v1, 0.f); }
                *(float2*)(C + (int64_t)r * ldc + c) = make_float2(v0, v1);
            }
        }
    }
}

// ---------------- host orchestration ----------------------------------------
static inline dim3 ggrid(int M, int N, int batch, int bm) {
    return dim3((unsigned)((N + 127) / 128), (unsigned)((M + bm - 1) / bm), (unsigned)batch);
}

extern "C" void kernel_launch(void* const* d_in, const int* in_sizes, int n_in,
                              void* d_out, int out_size)
{
    const int*   idx    = (const int*)  d_in[0];
    const float* tok_w  = (const float*)d_in[1];
    const float* pos    = (const float*)d_in[2];
    const float* ln1_s  = (const float*)d_in[3];
    const float* ln1_b  = (const float*)d_in[4];
    const float* wq     = (const float*)d_in[5];
    const float* wk     = (const float*)d_in[6];
    const float* wv     = (const float*)d_in[7];
    const float* wo     = (const float*)d_in[8];
    const float* bo     = (const float*)d_in[9];
    const float* ln2_s  = (const float*)d_in[10];
    const float* ln2_b  = (const float*)d_in[11];
    const float* w1     = (const float*)d_in[12];
    const float* b1     = (const float*)d_in[13];
    const float* w2     = (const float*)d_in[14];
    const float* b2     = (const float*)d_in[15];
    const float* lnf_s  = (const float*)d_in[16];
    const float* lnf_b  = (const float*)d_in[17];
    const float* head_w = (const float*)d_in[18];
    const float* head_b = (const float*)d_in[19];
    float* out = (float*)d_out;

    float *x, *h, *q, *k, *v, *o, *ff;
    cudaGetSymbolAddress((void**)&x,   g_x);
    cudaGetSymbolAddress((void**)&h,   g_h);
    cudaGetSymbolAddress((void**)&q,   g_q);
    cudaGetSymbolAddress((void**)&k,   g_k);
    cudaGetSymbolAddress((void**)&v,   g_v);
    cudaGetSymbolAddress((void**)&o,   g_o);
    cudaGetSymbolAddress((void**)&ff,  g_ff);

    const int M = Bq * Tq;                  // 2048
    const int flashSmem = FL_SMEM_WORDS * 4;
    cudaFuncSetAttribute(flash_kernel,
        cudaFuncAttributeMaxDynamicSharedMemorySize, flashSmem);

    // embedding
    embed_kernel<<<(M * Eq / 4 + 255) / 256, 256>>>(idx, tok_w, pos, x);

    for (int l = 0; l < Lq; l++) {
        const float* Wq = wq + (int64_t)l * Eq * Eq;
        const float* Wk = wk + (int64_t)l * Eq * Eq;
        const float* Wv = wv + (int64_t)l * Eq * Eq;
        const float* Wo = wo + (int64_t)l * Eq * Eq;
        const float* W1 = w1 + (int64_t)l * Eq * FFq;
        const float* W2 = w2 + (int64_t)l * FFq * Eq;

        // ln1
        ln_kernel<<<M, 256>>>(x, h, ln1_s + l * Eq, ln1_b + l * Eq);

        // fused q/k/v projections (z selects weight + output)
        gemm_tc<128><<<ggrid(M, Eq, 3, 128), 256>>>(h, Wq, q,
            M, Eq, Eq, Eq, Eq, Eq,
            nullptr, nullptr, 0, 1.0f,
            Wk, k, Wv, v);

        // fused flash attention: o = softmax(causal(qk^T/sqrt(d))) @ v
        flash_kernel<<<dim3(Tq / 128, Bq * Hq), 256, flashSmem>>>(q, k, v, o);

        // x = x + o @ Wo + bo
        gemm_tc<64><<<ggrid(M, Eq, 1, 64), 256>>>(o, Wo, x,
            M, Eq, Eq, Eq, Eq, Eq,
            bo + l * Eq, x, 0, 1.0f,
            nullptr, nullptr, nullptr, nullptr);

        // ln2
        ln_kernel<<<M, 256>>>(x, h, ln2_s + l * Eq, ln2_b + l * Eq);

        // ff = relu(h @ W1 + b1)
        gemm_tc<128><<<ggrid(M, FFq, 1, 128), 256>>>(h, W1, ff,
            M, FFq, Eq, Eq, FFq, FFq,
            b1 + l * FFq, nullptr, 1, 1.0f,
            nullptr, nullptr, nullptr, nullptr);

        // x = x + ff @ W2 + b2
        gemm_tc<64><<<ggrid(M, Eq, 1, 64), 256>>>(ff, W2, x,
            M, Eq, FFq, FFq, Eq, Eq,
            b2 + l * Eq, x, 0, 1.0f,
            nullptr, nullptr, nullptr, nullptr);
    }

    // final layernorm
    ln_kernel<<<M, 256>>>(x, h, lnf_s, lnf_b);

    // logits = h @ head_w + head_b
    gemm_tc<128><<<ggrid(M, Vq, 1, 128), 256>>>(h, head_w, out,
        M, Vq, Eq, Eq, Vq, Vq,
        head_b, nullptr, 0, 1.0f,
        nullptr, nullptr, nullptr, nullptr);
}